// round 12
// baseline (speedup 1.0000x reference)
#include <cuda_runtime.h>

#define T_LEN 5000
#define HID   64
#define BATCH 256

typedef unsigned long long u64t;

// ---- packed f32x2 helpers ----
__device__ __forceinline__ u64t pack2(float lo, float hi) {
    u64t d;
    asm("mov.b64 %0, {%1, %2};" : "=l"(d) : "f"(lo), "f"(hi));
    return d;
}
__device__ __forceinline__ void unpack2(u64t v, float& lo, float& hi) {
    asm("mov.b64 {%0, %1}, %2;" : "=f"(lo), "=f"(hi) : "l"(v));
}
__device__ __forceinline__ u64t ffma2(u64t a, u64t b, u64t c) {
    u64t d;
    asm("fma.rn.f32x2 %0, %1, %2, %3;" : "=l"(d) : "l"(a), "l"(b), "l"(c));
    return d;
}
__device__ __forceinline__ u64t add2(u64t a, u64t b) {
    u64t d;
    asm("add.rn.f32x2 %0, %1, %2;" : "=l"(d) : "l"(a), "l"(b));
    return d;
}
__device__ __forceinline__ u64t shfl_bfly1_u64(u64t v) {
    float lo, hi;
    unpack2(v, lo, hi);
    lo = __shfl_xor_sync(0xffffffffu, lo, 1);
    hi = __shfl_xor_sync(0xffffffffu, hi, 1);
    return pack2(lo, hi);
}

// ---- hardware tanh (sm_75+): single MUFU op ----
__device__ __forceinline__ float tanh_hw(float x) {
    float r;
    asm("tanh.approx.f32 %0, %1;" : "=f"(r) : "f"(x));
    return r;
}
// sigmoid(x) = 0.5*tanh(0.5x) + 0.5
__device__ __forceinline__ float sigmoid_hw(float x) {
    return fmaf(0.5f, tanh_hw(0.5f * x), 0.5f);
}

__global__ __launch_bounds__(128, 1)
void lstm_fused_kernel(const float* __restrict__ x,
                       const float* __restrict__ W_ih,
                       const float* __restrict__ W_hh,
                       const float* __restrict__ b_ih,
                       const float* __restrict__ b_hh,
                       const float* __restrict__ W_fc,
                       const float* __restrict__ b_fc,
                       float* __restrict__ out)
{
    // two batch rows per CTA — weights shared, states independent
    __shared__ __align__(16) float xA_sh[T_LEN];
    __shared__ __align__(16) float xB_sh[T_LEN];
    __shared__ __align__(16) float hA_sh[HID];
    __shared__ __align__(16) float hB_sh[HID];

    const int tid  = threadIdx.x;
    const int rowA = 2 * blockIdx.x;
    const int rowB = rowA + 1;

    // ---- stage both x rows into SMEM, coalesced float4 ----
    {
        const float4* xa = reinterpret_cast<const float4*>(x + rowA * T_LEN);
        const float4* xb = reinterpret_cast<const float4*>(x + rowB * T_LEN);
        float4* sa = reinterpret_cast<float4*>(xA_sh);
        float4* sb = reinterpret_cast<float4*>(xB_sh);
        for (int i = tid; i < T_LEN / 4; i += 128) { sa[i] = xa[i]; sb[i] = xb[i]; }
    }

    // ---- thread = (unit u, k-half): all 4 gates of u, 32 of 64 k each ----
    const int u    = tid >> 1;
    const int half = tid & 1;        // partner = lane^1, same warp
    const int kofs = half * 32;

    // ---- weights: 4 gate rows x 16 k-pairs -> 64 u64 regs (shared by rows) ----
    u64t w2[64];
    #pragma unroll
    for (int gi = 0; gi < 4; gi++) {
        const float4* wr =
            reinterpret_cast<const float4*>(W_hh + (gi * HID + u) * HID + kofs);
        #pragma unroll
        for (int j = 0; j < 8; j++) {
            float4 v = wr[j];
            w2[gi * 16 + 2 * j + 0] = pack2(v.x, v.y);
            w2[gi * 16 + 2 * j + 1] = pack2(v.z, v.w);
        }
    }

    // x-term + bias folded into chain init; only half==0 contributes them
    u64t wih2[4], b2[4];
    #pragma unroll
    for (int gi = 0; gi < 4; gi++) {
        const int r = gi * HID + u;
        wih2[gi] = half ? 0ULL : pack2(W_ih[r], 0.0f);
        b2[gi]   = half ? 0ULL : pack2(b_ih[r] + b_hh[r], 0.0f);
    }

    if (tid < HID) { hA_sh[tid] = 0.0f; hB_sh[tid] = 0.0f; }
    float cA = 0.0f, cB = 0.0f;      // redundant in both partner lanes
    __syncthreads();

    const ulonglong2* hpA = reinterpret_cast<const ulonglong2*>(hA_sh + kofs);
    const ulonglong2* hpB = reinterpret_cast<const ulonglong2*>(hB_sh + kofs);

    // ================= recurrence: 5000 serial steps, 2 rows =================
    for (int t = 0; t < T_LEN; t++) {
        const u64t xa2 = pack2(xA_sh[t], xA_sh[t]);
        const u64t xb2 = pack2(xB_sh[t], xB_sh[t]);

        // 8 independent chains (4 gates x 2 rows) — tails of one row hide
        // under the other row's FFMA2 stream
        u64t Ai = ffma2(xa2, wih2[0], b2[0]);
        u64t Af = ffma2(xa2, wih2[1], b2[1]);
        u64t Ag = ffma2(xa2, wih2[2], b2[2]);
        u64t Ao = ffma2(xa2, wih2[3], b2[3]);
        u64t Bi = ffma2(xb2, wih2[0], b2[0]);
        u64t Bf = ffma2(xb2, wih2[1], b2[1]);
        u64t Bg = ffma2(xb2, wih2[2], b2[2]);
        u64t Bo = ffma2(xb2, wih2[3], b2[3]);

        #pragma unroll
        for (int j = 0; j < 8; j++) {
            ulonglong2 ha = hpA[j];
            ulonglong2 hb = hpB[j];
            Ai = ffma2(ha.x, w2[ 0 + 2 * j], Ai);
            Ai = ffma2(ha.y, w2[ 1 + 2 * j], Ai);
            Af = ffma2(ha.x, w2[16 + 2 * j], Af);
            Af = ffma2(ha.y, w2[17 + 2 * j], Af);
            Ag = ffma2(ha.x, w2[32 + 2 * j], Ag);
            Ag = ffma2(ha.y, w2[33 + 2 * j], Ag);
            Ao = ffma2(ha.x, w2[48 + 2 * j], Ao);
            Ao = ffma2(ha.y, w2[49 + 2 * j], Ao);
            Bi = ffma2(hb.x, w2[ 0 + 2 * j], Bi);
            Bi = ffma2(hb.y, w2[ 1 + 2 * j], Bi);
            Bf = ffma2(hb.x, w2[16 + 2 * j], Bf);
            Bf = ffma2(hb.y, w2[17 + 2 * j], Bf);
            Bg = ffma2(hb.x, w2[32 + 2 * j], Bg);
            Bg = ffma2(hb.y, w2[33 + 2 * j], Bg);
            Bo = ffma2(hb.x, w2[48 + 2 * j], Bo);
            Bo = ffma2(hb.y, w2[49 + 2 * j], Bo);
        }

        // ---- row A tail ----
        {
            float l, h2;
            unpack2(Ai, l, h2); const float pi_p = l + h2;
            unpack2(Af, l, h2); const float pf_p = l + h2;
            unpack2(Ag, l, h2); const float pg_p = l + h2;
            unpack2(Ao, l, h2); const float po_p = l + h2;
            u64t s_if = pack2(pi_p, pf_p);
            u64t s_go = pack2(pg_p, po_p);
            s_if = add2(s_if, shfl_bfly1_u64(s_if));
            s_go = add2(s_go, shfl_bfly1_u64(s_go));
            float pi, pf, pg, po;
            unpack2(s_if, pi, pf);
            unpack2(s_go, pg, po);
            const float iv = sigmoid_hw(pi);
            const float fv = sigmoid_hw(pf);
            const float gv = tanh_hw(pg);
            const float ov = sigmoid_hw(po);
            cA = fmaf(fv, cA, iv * gv);
            const float hval = ov * tanh_hw(cA);
            if (!half) hA_sh[u] = hval;
        }
        // ---- row B tail ----
        {
            float l, h2;
            unpack2(Bi, l, h2); const float pi_p = l + h2;
            unpack2(Bf, l, h2); const float pf_p = l + h2;
            unpack2(Bg, l, h2); const float pg_p = l + h2;
            unpack2(Bo, l, h2); const float po_p = l + h2;
            u64t s_if = pack2(pi_p, pf_p);
            u64t s_go = pack2(pg_p, po_p);
            s_if = add2(s_if, shfl_bfly1_u64(s_if));
            s_go = add2(s_go, shfl_bfly1_u64(s_go));
            float pi, pf, pg, po;
            unpack2(s_if, pi, pf);
            unpack2(s_go, pg, po);
            const float iv = sigmoid_hw(pi);
            const float fv = sigmoid_hw(pf);
            const float gv = tanh_hw(pg);
            const float ov = sigmoid_hw(po);
            cB = fmaf(fv, cB, iv * gv);
            const float hval = ov * tanh_hw(cB);
            if (!half) hB_sh[u] = hval;
        }
        __syncthreads();             // single barrier covers both rows
    }

    // ================= FC(64 -> 128) + ReLU, both rows =================
    {
        const float4* wr = reinterpret_cast<const float4*>(W_fc + tid * HID);
        float accA = b_fc[tid];
        float accB = accA;
        #pragma unroll
        for (int i = 0; i < HID / 4; i++) {
            float4 w = wr[i];
            accA += hA_sh[4 * i + 0] * w.x + hA_sh[4 * i + 1] * w.y
                  + hA_sh[4 * i + 2] * w.z + hA_sh[4 * i + 3] * w.w;
            accB += hB_sh[4 * i + 0] * w.x + hB_sh[4 * i + 1] * w.y
                  + hB_sh[4 * i + 2] * w.z + hB_sh[4 * i + 3] * w.w;
        }
        out[rowA * 128 + tid] = fmaxf(accA, 0.0f);
        out[rowB * 128 + tid] = fmaxf(accB, 0.0f);
    }
}

extern "C" void kernel_launch(void* const* d_in, const int* in_sizes, int n_in,
                              void* d_out, int out_size)
{
    const float* x    = (const float*)d_in[0];
    const float* W_ih = (const float*)d_in[1];
    const float* W_hh = (const float*)d_in[2];
    const float* b_ih = (const float*)d_in[3];
    const float* b_hh = (const float*)d_in[4];
    const float* W_fc = (const float*)d_in[5];
    const float* b_fc = (const float*)d_in[6];

    lstm_fused_kernel<<<BATCH / 2, 128>>>(x, W_ih, W_hh, b_ih, b_hh,
                                          W_fc, b_fc, (float*)d_out);
}